// round 1
// baseline (speedup 1.0000x reference)
#include <cuda_runtime.h>
#include <cuda_bf16.h>
#include <cstdint>

namespace {

constexpr int Bn = 2, Hn = 16, SQn = 2048, SKn = 2048, Dn = 128;
constexpr int STRIDE_W = 68;             // 32-bit words per padded smem row (128 bf16 + 8 pad)
constexpr int TILE_W   = 128 * STRIDE_W; // words per tile buffer (34816 B)
constexpr float SCALE  = 22.62741699796952f; // 2 * sqrt(128): qk*sqrt(D) then /(1-0.5)

__device__ __forceinline__ uint32_t packbf(float a, float b) {
    __nv_bfloat162 t = __floats2bfloat162_rn(a, b);
    return *reinterpret_cast<uint32_t*>(&t);
}
__device__ __forceinline__ float bfhi(float x) {
    return __bfloat162float(__float2bfloat16_rn(x));
}
__device__ __forceinline__ void mma16816(float* d, const uint32_t* a, uint32_t b0, uint32_t b1) {
    asm volatile(
        "mma.sync.aligned.m16n8k16.row.col.f32.bf16.bf16.f32 "
        "{%0,%1,%2,%3}, {%4,%5,%6,%7}, {%8,%9}, {%0,%1,%2,%3};\n"
        : "+f"(d[0]), "+f"(d[1]), "+f"(d[2]), "+f"(d[3])
        : "r"(a[0]), "r"(a[1]), "r"(a[2]), "r"(a[3]), "r"(b0), "r"(b1));
}

__global__ __launch_bounds__(256, 1) void attn_kernel(
    const float* __restrict__ Q, const float* __restrict__ K,
    const float* __restrict__ V, const int* __restrict__ M,
    float* __restrict__ O)
{
    extern __shared__ uint32_t smem[];
    uint32_t* Qh = smem;
    uint32_t* Ql = Qh + TILE_W;
    uint32_t* Kh = Ql + TILE_W;
    uint32_t* Kl = Kh + TILE_W;
    uint32_t* Vh = Kl + TILE_W;
    uint32_t* Vl = Vh + TILE_W;

    const int tid  = threadIdx.x;
    const int warp = tid >> 5, lane = tid & 31;
    const int gid  = lane >> 2, qid = lane & 3;   // groupID, thread-in-group
    const int qr   = warp * 16;                   // warp's q-row base within tile

    const size_t bh = blockIdx.y;
    const int    qt = blockIdx.x;

    const float* Qg = Q + (bh * SQn + (size_t)qt * 128) * Dn;
    const int*   Mg = M + (bh * SQn + (size_t)qt * 128) * SKn;
    float*       Og = O + (bh * SQn + (size_t)qt * 128) * Dn;

    // ---- load Q tile once: fp32 -> bf16 hi/lo, padded row stride ----
    {
        const float4* src = reinterpret_cast<const float4*>(Qg);
        #pragma unroll
        for (int it = 0; it < 16; ++it) {
            int idx = tid + it * 256;          // 0..4095 float4s
            int row = idx >> 5, c4 = idx & 31;
            float4 v = src[idx];
            float h0 = bfhi(v.x), h1 = bfhi(v.y), h2 = bfhi(v.z), h3 = bfhi(v.w);
            int off = row * STRIDE_W + c4 * 2;
            Qh[off]   = packbf(h0, h1);
            Qh[off+1] = packbf(h2, h3);
            Ql[off]   = packbf(v.x - h0, v.y - h1);
            Ql[off+1] = packbf(v.z - h2, v.w - h3);
        }
    }

    float o[16][4];
    #pragma unroll
    for (int i = 0; i < 16; ++i) {
        #pragma unroll
        for (int j = 0; j < 4; ++j) o[i][j] = 0.f;
    }

    for (int kt = 0; kt < 16; ++kt) {
        __syncthreads();  // previous iteration's smem reads done

        // ---- load K tile [key][d] hi/lo ----
        {
            const float4* src = reinterpret_cast<const float4*>(K + (bh * SKn + (size_t)kt * 128) * Dn);
            #pragma unroll
            for (int it = 0; it < 16; ++it) {
                int idx = tid + it * 256;
                int row = idx >> 5, c4 = idx & 31;
                float4 v = src[idx];
                float h0 = bfhi(v.x), h1 = bfhi(v.y), h2 = bfhi(v.z), h3 = bfhi(v.w);
                int off = row * STRIDE_W + c4 * 2;
                Kh[off]   = packbf(h0, h1);
                Kh[off+1] = packbf(h2, h3);
                Kl[off]   = packbf(v.x - h0, v.y - h1);
                Kl[off+1] = packbf(v.z - h2, v.w - h3);
            }
        }
        // ---- load V tile transposed [d][key] hi/lo ----
        {
            const float4* src = reinterpret_cast<const float4*>(V + (bh * SKn + (size_t)kt * 128) * Dn);
            __nv_bfloat16* vh = reinterpret_cast<__nv_bfloat16*>(Vh);
            __nv_bfloat16* vl = reinterpret_cast<__nv_bfloat16*>(Vl);
            #pragma unroll
            for (int it = 0; it < 16; ++it) {
                int idx = tid + it * 256;
                int key = idx >> 5, c4 = idx & 31;
                float4 v = src[idx];
                int d0 = c4 * 4;
                float h;
                h = bfhi(v.x); vh[(d0+0)*136 + key] = __float2bfloat16_rn(h); vl[(d0+0)*136 + key] = __float2bfloat16_rn(v.x - h);
                h = bfhi(v.y); vh[(d0+1)*136 + key] = __float2bfloat16_rn(h); vl[(d0+1)*136 + key] = __float2bfloat16_rn(v.y - h);
                h = bfhi(v.z); vh[(d0+2)*136 + key] = __float2bfloat16_rn(h); vl[(d0+2)*136 + key] = __float2bfloat16_rn(v.z - h);
                h = bfhi(v.w); vh[(d0+3)*136 + key] = __float2bfloat16_rn(h); vl[(d0+3)*136 + key] = __float2bfloat16_rn(v.w - h);
            }
        }
        __syncthreads();

        const int koff = kt * 128;
        #pragma unroll 1
        for (int nc = 0; nc < 4; ++nc) {       // 32-key chunks
            const int kb = nc * 32;

            // prefetch mask ints for this chunk (hide DRAM latency under S compute)
            const int* m0 = Mg + (size_t)(qr + gid) * SKn + koff + kb + qid * 2;
            const int* m1 = m0 + 8 * (size_t)SKn;
            int2 ma[4], mb[4];
            #pragma unroll
            for (int j = 0; j < 4; ++j) {
                ma[j] = *reinterpret_cast<const int2*>(m0 + j * 8);
                mb[j] = *reinterpret_cast<const int2*>(m1 + j * 8);
            }

            // ---- GEMM1: S[16q x 32k] = Q * K^T  (bf16x3 split) ----
            float s[4][4];
            #pragma unroll
            for (int j = 0; j < 4; ++j) { s[j][0]=0.f; s[j][1]=0.f; s[j][2]=0.f; s[j][3]=0.f; }

            #pragma unroll
            for (int ds = 0; ds < 8; ++ds) {
                uint32_t ah[4], al[4];
                int ao = (qr + gid) * STRIDE_W + ds * 8 + qid;
                ah[0] = Qh[ao];                      ah[1] = Qh[ao + 8*STRIDE_W];
                ah[2] = Qh[ao + 4];                  ah[3] = Qh[ao + 8*STRIDE_W + 4];
                al[0] = Ql[ao];                      al[1] = Ql[ao + 8*STRIDE_W];
                al[2] = Ql[ao + 4];                  al[3] = Ql[ao + 8*STRIDE_W + 4];
                #pragma unroll
                for (int j = 0; j < 4; ++j) {
                    int bo = (kb + j*8 + gid) * STRIDE_W + ds * 8 + qid;
                    uint32_t b0h = Kh[bo], b1h = Kh[bo + 4];
                    uint32_t b0l = Kl[bo], b1l = Kl[bo + 4];
                    mma16816(s[j], ah, b0h, b1h);
                    mma16816(s[j], al, b0h, b1h);
                    mma16816(s[j], ah, b0l, b1l);
                }
            }

            // ---- mask + scale -> P (registers only) ----
            float p[4][4];
            #pragma unroll
            for (int j = 0; j < 4; ++j) {
                p[j][0] = ma[j].x ? s[j][0] * SCALE : 0.f;
                p[j][1] = ma[j].y ? s[j][1] * SCALE : 0.f;
                p[j][2] = mb[j].x ? s[j][2] * SCALE : 0.f;
                p[j][3] = mb[j].y ? s[j][3] * SCALE : 0.f;
            }

            // ---- GEMM2: O[16q x 128d] += P[16 x 32] * V[32 x 128] ----
            #pragma unroll
            for (int kk = 0; kk < 2; ++kk) {   // two k=16 steps
                uint32_t ahi[4], alo[4];
                {
                    const float* p0 = p[kk*2 + 0];
                    const float* p1 = p[kk*2 + 1];
                    float h00=bfhi(p0[0]), h01=bfhi(p0[1]), h02=bfhi(p0[2]), h03=bfhi(p0[3]);
                    float h10=bfhi(p1[0]), h11=bfhi(p1[1]), h12=bfhi(p1[2]), h13=bfhi(p1[3]);
                    ahi[0]=packbf(h00,h01);             ahi[1]=packbf(h02,h03);
                    ahi[2]=packbf(h10,h11);             ahi[3]=packbf(h12,h13);
                    alo[0]=packbf(p0[0]-h00,p0[1]-h01); alo[1]=packbf(p0[2]-h02,p0[3]-h03);
                    alo[2]=packbf(p1[0]-h10,p1[1]-h11); alo[3]=packbf(p1[2]-h12,p1[3]-h13);
                }
                const int vbase = kb/2 + kk*8 + qid;
                #pragma unroll
                for (int nd = 0; nd < 16; ++nd) {
                    int vo = (nd*8 + gid) * STRIDE_W + vbase;
                    uint32_t v0h = Vh[vo], v1h = Vh[vo + 4];
                    uint32_t v0l = Vl[vo], v1l = Vl[vo + 4];
                    mma16816(o[nd], ahi, v0h, v1h);
                    mma16816(o[nd], alo, v0h, v1h);
                    mma16816(o[nd], ahi, v0l, v1l);
                }
            }
        }
    }

    // ---- epilogue: write O (fp32) ----
    float* o0 = Og + (size_t)(qr + gid) * Dn + qid * 2;
    float* o1 = o0 + 8 * Dn;
    #pragma unroll
    for (int nd = 0; nd < 16; ++nd) {
        *reinterpret_cast<float2*>(o0 + nd * 8) = make_float2(o[nd][0], o[nd][1]);
        *reinterpret_cast<float2*>(o1 + nd * 8) = make_float2(o[nd][2], o[nd][3]);
    }
}

} // namespace

extern "C" void kernel_launch(void* const* d_in, const int* in_sizes, int n_in,
                              void* d_out, int out_size) {
    (void)in_sizes; (void)n_in; (void)out_size;
    const float* Q = (const float*)d_in[0];
    const float* K = (const float*)d_in[1];
    const float* V = (const float*)d_in[2];
    const int*   M = (const int*)d_in[3];
    float*       O = (float*)d_out;

    const int smem_bytes = 6 * TILE_W * 4;  // 208896 B
    cudaFuncSetAttribute(attn_kernel, cudaFuncAttributeMaxDynamicSharedMemorySize, smem_bytes);

    dim3 grid(SQn / 128, Bn * Hn);
    attn_kernel<<<grid, 256, smem_bytes>>>(Q, K, V, M, O);
}

// round 2
// speedup vs baseline: 1.9985x; 1.9985x over previous
#include <cuda_runtime.h>
#include <cuda_bf16.h>
#include <cstdint>

namespace {

constexpr int Bn = 2, Hn = 16, SQn = 2048, SKn = 2048, Dn = 128;
constexpr int STRIDE_W = 68;             // 32-bit words per padded smem row (128 bf16 + 8 pad)
constexpr int STRIDE_B = STRIDE_W * 4;   // 272 bytes
constexpr int TILE_W   = 128 * STRIDE_W; // words per tile buffer (34816 B)
constexpr int TILE_B   = TILE_W * 4;
constexpr float SCALE  = 22.62741699796952f; // 2 * sqrt(128)

__device__ __forceinline__ uint32_t packbf(float a, float b) {
    __nv_bfloat162 t = __floats2bfloat162_rn(a, b);
    return *reinterpret_cast<uint32_t*>(&t);
}
__device__ __forceinline__ uint32_t prmt_hi(uint32_t a, uint32_t b) {
    uint32_t d;
    asm("prmt.b32 %0,%1,%2,0x7632;" : "=r"(d) : "r"(a), "r"(b));
    return d;
}
__device__ __forceinline__ void mma16816(float* d, const uint32_t* a, uint32_t b0, uint32_t b1) {
    asm volatile(
        "mma.sync.aligned.m16n8k16.row.col.f32.bf16.bf16.f32 "
        "{%0,%1,%2,%3}, {%4,%5,%6,%7}, {%8,%9}, {%0,%1,%2,%3};\n"
        : "+f"(d[0]), "+f"(d[1]), "+f"(d[2]), "+f"(d[3])
        : "r"(a[0]), "r"(a[1]), "r"(a[2]), "r"(a[3]), "r"(b0), "r"(b1));
}
__device__ __forceinline__ void ldsm4(uint32_t* r, uint32_t saddr) {
    asm volatile("ldmatrix.sync.aligned.m8n8.x4.shared.b16 {%0,%1,%2,%3}, [%4];\n"
                 : "=r"(r[0]), "=r"(r[1]), "=r"(r[2]), "=r"(r[3]) : "r"(saddr));
}
__device__ __forceinline__ void ldsm4t(uint32_t* r, uint32_t saddr) {
    asm volatile("ldmatrix.sync.aligned.m8n8.x4.trans.shared.b16 {%0,%1,%2,%3}, [%4];\n"
                 : "=r"(r[0]), "=r"(r[1]), "=r"(r[2]), "=r"(r[3]) : "r"(saddr));
}

// fp32 -> (hi=trunc-bf16, lo=rn-bf16 of remainder) split, row-major padded tile
__device__ __forceinline__ void cvt_store_tile(uint32_t* H, uint32_t* L,
                                               const float4* __restrict__ src, int tid) {
    #pragma unroll
    for (int it = 0; it < 16; ++it) {
        int idx = tid + it * 256;            // 0..4095 float4s
        int row = idx >> 5, c4 = idx & 31;
        float4 v = src[idx];
        uint32_t bx = __float_as_uint(v.x), by = __float_as_uint(v.y);
        uint32_t bz = __float_as_uint(v.z), bw = __float_as_uint(v.w);
        uint32_t h0 = prmt_hi(bx, by);
        uint32_t h1 = prmt_hi(bz, bw);
        float lx = v.x - __uint_as_float(bx & 0xFFFF0000u);
        float ly = v.y - __uint_as_float(by & 0xFFFF0000u);
        float lz = v.z - __uint_as_float(bz & 0xFFFF0000u);
        float lw = v.w - __uint_as_float(bw & 0xFFFF0000u);
        int off = row * STRIDE_W + c4 * 2;
        *reinterpret_cast<uint2*>(H + off) = make_uint2(h0, h1);
        *reinterpret_cast<uint2*>(L + off) = make_uint2(packbf(lx, ly), packbf(lz, lw));
    }
}

__global__ __launch_bounds__(256, 1) void attn_kernel(
    const float* __restrict__ Q, const float* __restrict__ K,
    const float* __restrict__ V, const int* __restrict__ M,
    float* __restrict__ O)
{
    extern __shared__ uint32_t smem[];
    uint32_t* Qh = smem;
    uint32_t* Ql = Qh + TILE_W;
    uint32_t* Kh = Ql + TILE_W;
    uint32_t* Kl = Kh + TILE_W;
    uint32_t* Vh = Kl + TILE_W;
    uint32_t* Vl = Vh + TILE_W;

    const uint32_t sbase = (uint32_t)__cvta_generic_to_shared(smem);
    const uint32_t sQh = sbase;
    const uint32_t sQl = sQh + TILE_B;
    const uint32_t sKh = sQl + TILE_B;
    const uint32_t sKl = sKh + TILE_B;
    const uint32_t sVh = sKl + TILE_B;
    const uint32_t sVl = sVh + TILE_B;

    const int tid  = threadIdx.x;
    const int warp = tid >> 5, lane = tid & 31;
    const int gid  = lane >> 2, qid = lane & 3;
    const int qr   = warp * 16;

    const size_t bh = blockIdx.y;
    const int    qt = blockIdx.x;

    const float* Qg = Q + (bh * SQn + (size_t)qt * 128) * Dn;
    const int*   Mg = M + (bh * SQn + (size_t)qt * 128) * SKn;
    float*       Og = O + (bh * SQn + (size_t)qt * 128) * Dn;

    // lane-derived ldmatrix address offsets (bytes)
    const uint32_t bkOff = ((lane & 7) + ((lane >> 4) & 1) * 8) * STRIDE_B + ((lane >> 3) & 1) * 16;
    const uint32_t vOff  = ((lane & 7) + ((lane >> 3) & 1) * 8) * STRIDE_B + ((lane >> 4) & 1) * 16;
    const uint32_t qOff  = (qr + (lane & 15)) * STRIDE_B + ((lane >> 4) & 1) * 16;

    // ---- Q tile: global -> smem (hi/lo) ----
    cvt_store_tile(Qh, Ql, reinterpret_cast<const float4*>(Qg), tid);
    __syncthreads();

    // ---- hoist Q fragments into registers (invariant across all K tiles) ----
    uint32_t qfh[8][4], qfl[8][4];
    #pragma unroll
    for (int ds = 0; ds < 8; ++ds) {
        ldsm4(qfh[ds], sQh + qOff + ds * 32);
        ldsm4(qfl[ds], sQl + qOff + ds * 32);
    }

    float o[16][4];
    #pragma unroll
    for (int i = 0; i < 16; ++i) {
        #pragma unroll
        for (int j = 0; j < 4; ++j) o[i][j] = 0.f;
    }

    #pragma unroll 1
    for (int kt = 0; kt < 16; ++kt) {
        __syncthreads();  // previous iteration's smem reads done
        cvt_store_tile(Kh, Kl, reinterpret_cast<const float4*>(K + (bh * SKn + (size_t)kt * 128) * Dn), tid);
        cvt_store_tile(Vh, Vl, reinterpret_cast<const float4*>(V + (bh * SKn + (size_t)kt * 128) * Dn), tid);
        __syncthreads();

        const int koff = kt * 128;
        #pragma unroll 1
        for (int nc = 0; nc < 4; ++nc) {       // 32-key chunks
            const int kb = nc * 32;

            // prefetch mask ints for this chunk
            const int* m0 = Mg + (size_t)(qr + gid) * SKn + koff + kb + qid * 2;
            const int* m1 = m0 + 8 * (size_t)SKn;
            int2 ma[4], mb[4];
            #pragma unroll
            for (int j = 0; j < 4; ++j) {
                ma[j] = *reinterpret_cast<const int2*>(m0 + j * 8);
                mb[j] = *reinterpret_cast<const int2*>(m1 + j * 8);
            }

            // ---- GEMM1: S[16q x 32k] = Q * K^T (bf16x3 split) ----
            float s[4][4];
            #pragma unroll
            for (int j = 0; j < 4; ++j) { s[j][0]=0.f; s[j][1]=0.f; s[j][2]=0.f; s[j][3]=0.f; }

            #pragma unroll
            for (int ds = 0; ds < 8; ++ds) {
                uint32_t bh0[4], bh1[4], bl0[4], bl1[4];
                const uint32_t kcol = bkOff + ds * 32;
                ldsm4(bh0, sKh + (uint32_t)(kb      ) * STRIDE_B + kcol);
                ldsm4(bh1, sKh + (uint32_t)(kb + 16) * STRIDE_B + kcol);
                ldsm4(bl0, sKl + (uint32_t)(kb      ) * STRIDE_B + kcol);
                ldsm4(bl1, sKl + (uint32_t)(kb + 16) * STRIDE_B + kcol);
                mma16816(s[0], qfh[ds], bh0[0], bh0[1]);
                mma16816(s[1], qfh[ds], bh0[2], bh0[3]);
                mma16816(s[2], qfh[ds], bh1[0], bh1[1]);
                mma16816(s[3], qfh[ds], bh1[2], bh1[3]);
                mma16816(s[0], qfl[ds], bh0[0], bh0[1]);
                mma16816(s[1], qfl[ds], bh0[2], bh0[3]);
                mma16816(s[2], qfl[ds], bh1[0], bh1[1]);
                mma16816(s[3], qfl[ds], bh1[2], bh1[3]);
                mma16816(s[0], qfh[ds], bl0[0], bl0[1]);
                mma16816(s[1], qfh[ds], bl0[2], bl0[3]);
                mma16816(s[2], qfh[ds], bl1[0], bl1[1]);
                mma16816(s[3], qfh[ds], bl1[2], bl1[3]);
            }

            // ---- mask + scale -> P (registers only) ----
            float p[4][4];
            #pragma unroll
            for (int j = 0; j < 4; ++j) {
                p[j][0] = ma[j].x ? s[j][0] * SCALE : 0.f;
                p[j][1] = ma[j].y ? s[j][1] * SCALE : 0.f;
                p[j][2] = mb[j].x ? s[j][2] * SCALE : 0.f;
                p[j][3] = mb[j].y ? s[j][3] * SCALE : 0.f;
            }

            // ---- GEMM2: O[16q x 128d] += P[16 x 32] * V[32 x 128] ----
            #pragma unroll
            for (int kk = 0; kk < 2; ++kk) {
                uint32_t ahi[4], alo[4];
                {
                    const float* p0 = p[kk*2 + 0];
                    const float* p1 = p[kk*2 + 1];
                    uint32_t b00=__float_as_uint(p0[0]), b01=__float_as_uint(p0[1]);
                    uint32_t b02=__float_as_uint(p0[2]), b03=__float_as_uint(p0[3]);
                    uint32_t b10=__float_as_uint(p1[0]), b11=__float_as_uint(p1[1]);
                    uint32_t b12=__float_as_uint(p1[2]), b13=__float_as_uint(p1[3]);
                    ahi[0] = prmt_hi(b00, b01);
                    ahi[1] = prmt_hi(b02, b03);
                    ahi[2] = prmt_hi(b10, b11);
                    ahi[3] = prmt_hi(b12, b13);
                    alo[0] = packbf(p0[0] - __uint_as_float(b00 & 0xFFFF0000u),
                                    p0[1] - __uint_as_float(b01 & 0xFFFF0000u));
                    alo[1] = packbf(p0[2] - __uint_as_float(b02 & 0xFFFF0000u),
                                    p0[3] - __uint_as_float(b03 & 0xFFFF0000u));
                    alo[2] = packbf(p1[0] - __uint_as_float(b10 & 0xFFFF0000u),
                                    p1[1] - __uint_as_float(b11 & 0xFFFF0000u));
                    alo[3] = packbf(p1[2] - __uint_as_float(b12 & 0xFFFF0000u),
                                    p1[3] - __uint_as_float(b13 & 0xFFFF0000u));
                }
                const uint32_t vbase = (uint32_t)(kb + kk * 16) * STRIDE_B + vOff;
                #pragma unroll
                for (int t = 0; t < 8; ++t) {
                    uint32_t vh[4], vl[4];
                    ldsm4t(vh, sVh + vbase + t * 32);
                    ldsm4t(vl, sVl + vbase + t * 32);
                    mma16816(o[2*t    ], ahi, vh[0], vh[1]);
                    mma16816(o[2*t + 1], ahi, vh[2], vh[3]);
                    mma16816(o[2*t    ], alo, vh[0], vh[1]);
                    mma16816(o[2*t + 1], alo, vh[2], vh[3]);
                    mma16816(o[2*t    ], ahi, vl[0], vl[1]);
                    mma16816(o[2*t + 1], ahi, vl[2], vl[3]);
                }
            }
        }
    }

    // ---- epilogue: write O (fp32) ----
    float* o0 = Og + (size_t)(qr + gid) * Dn + qid * 2;
    float* o1 = o0 + 8 * Dn;
    #pragma unroll
    for (int nd = 0; nd < 16; ++nd) {
        *reinterpret_cast<float2*>(o0 + nd * 8) = make_float2(o[nd][0], o[nd][1]);
        *reinterpret_cast<float2*>(o1 + nd * 8) = make_float2(o[nd][2], o[nd][3]);
    }
}

} // namespace

extern "C" void kernel_launch(void* const* d_in, const int* in_sizes, int n_in,
                              void* d_out, int out_size) {
    (void)in_sizes; (void)n_in; (void)out_size;
    const float* Q = (const float*)d_in[0];
    const float* K = (const float*)d_in[1];
    const float* V = (const float*)d_in[2];
    const int*   M = (const int*)d_in[3];
    float*       O = (float*)d_out;

    const int smem_bytes = 6 * TILE_B;  // 208896 B
    cudaFuncSetAttribute(attn_kernel, cudaFuncAttributeMaxDynamicSharedMemorySize, smem_bytes);

    dim3 grid(SQn / 128, Bn * Hn);
    attn_kernel<<<grid, 256, smem_bytes>>>(Q, K, V, M, O);
}